// round 12
// baseline (speedup 1.0000x reference)
#include <cuda_runtime.h>
#include <cuda_bf16.h>
#include <cstdint>
#include <math.h>

// Problem constants
#define BB 4
#define SS 1024
#define DD 1024
#define BS (BB*SS)                  // 4096 rows total
#define ELEMS ((size_t)BB*SS*DD)    // 4194304  (== B*S*S too)
#define NW (DD*DD)

// ============================================================================
// GEMM tiling
// ============================================================================
#define BM 128
#define BN 128
#define BK 32
#define ASTRIDE 40                      // bf16 elems per smem row (80 bytes)
#define TILE_B (128*ASTRIDE*2)          // 10240 bytes per tile (128 rows x 80B)
#define STAGE_B (4*TILE_B)              // Ah, Al, Bh, Bl = 40960 B
#define NSTAGE 3
#define SMEM_REQ (NSTAGE*STAGE_B)       // 122880 B

__device__ __forceinline__ uint32_t smem_to_u32(const void* smem_ptr) {
    uint32_t addr;
    asm("{ .reg .u64 tmp; cvta.to.shared.u64 tmp, %1; cvt.u32.u64 %0, tmp; }"
        : "=r"(addr) : "l"(smem_ptr));
    return addr;
}
__device__ __forceinline__ void ldsm4(uint32_t* r, uint32_t addr) {
    asm volatile("ldmatrix.sync.aligned.m8n8.x4.shared.b16 {%0,%1,%2,%3}, [%4];"
                 : "=r"(r[0]), "=r"(r[1]), "=r"(r[2]), "=r"(r[3]) : "r"(addr));
}
__device__ __forceinline__ void mma_bf16(float* c, const uint32_t* a, const uint32_t* b) {
    asm volatile(
        "mma.sync.aligned.m16n8k16.row.col.f32.bf16.bf16.f32 "
        "{%0,%1,%2,%3}, {%4,%5,%6,%7}, {%8,%9}, {%0,%1,%2,%3};"
        : "+f"(c[0]), "+f"(c[1]), "+f"(c[2]), "+f"(c[3])
        : "r"(a[0]), "r"(a[1]), "r"(a[2]), "r"(a[3]), "r"(b[0]), "r"(b[1]));
}
__device__ __forceinline__ void cp_async16(uint32_t dst, const void* src) {
    asm volatile("cp.async.cg.shared.global [%0], [%1], 16;" :: "r"(dst), "l"(src));
}
#define CP_COMMIT() asm volatile("cp.async.commit_group;" ::: "memory")
#define CP_WAIT1()  asm volatile("cp.async.wait_group 1;" ::: "memory")

// ============================================================================
// Scratch (no allocation allowed) — merged contiguous regions for z-batching
// ============================================================================
__device__ __nv_bfloat16 g_Xh[3*ELEMS], g_Xl[3*ELEMS];   // q,k,v inputs split
__device__ __nv_bfloat16 g_Wh[4*NW],    g_Wl[4*NW];      // Wq,Wk,Wv,Wo split
__device__ __nv_bfloat16 g_Ph[3*ELEMS], g_Pl[3*ELEMS];   // Q,K,V projections split
__device__ __nv_bfloat16 g_Vth[ELEMS],  g_Vtl[ELEMS];    // V^T split
__device__ __nv_bfloat16 g_Ah[ELEMS],   g_Al[ELEMS];     // attn split
__device__ __nv_bfloat16 g_AVh[ELEMS],  g_AVl[ELEMS];    // attn@V split
__device__ float g_Sq[BS], g_Tq[BS], g_Sk[BS], g_Tk[BS];

// ============================================================================
// Entropy stats: Sq[r]=sum exp(tanh(q[r,m])), Tq[r]=sum x*exp(x), m<8
// ============================================================================
__global__ void stats_kernel(const float* __restrict__ q, const float* __restrict__ k,
                             float* __restrict__ Sq, float* __restrict__ Tq,
                             float* __restrict__ Sk, float* __restrict__ Tk)
{
    int r = blockIdx.x * blockDim.x + threadIdx.x;
    if (r >= BS) return;
    float s = 0.f, t = 0.f;
    #pragma unroll
    for (int m = 0; m < 8; m++) {
        float x = tanhf(q[(size_t)r * DD + m]);
        float e = expf(x);
        s += e; t += x * e;
    }
    Sq[r] = s; Tq[r] = t;
    s = 0.f; t = 0.f;
    #pragma unroll
    for (int m = 0; m < 8; m++) {
        float x = tanhf(k[(size_t)r * DD + m]);
        float e = expf(x);
        s += e; t += x * e;
    }
    Sk[r] = s; Tk[r] = t;
}

// ============================================================================
// fp32 -> (hi, lo) bf16 split; z selects one of up to 4 sources
// ============================================================================
__global__ void convert_kernel(const float* __restrict__ x0, const float* __restrict__ x1,
                               const float* __restrict__ x2, const float* __restrict__ x3,
                               __nv_bfloat16* __restrict__ hi,
                               __nv_bfloat16* __restrict__ lo, int n)
{
    const int z = blockIdx.z;
    const float* x = (z == 0) ? x0 : (z == 1) ? x1 : (z == 2) ? x2 : x3;
    __nv_bfloat16* h = hi + (size_t)z * n;
    __nv_bfloat16* l = lo + (size_t)z * n;
    int i = (blockIdx.x * blockDim.x + threadIdx.x) * 4;
    if (i >= n) return;
    float4 v = *reinterpret_cast<const float4*>(x + i);
    float f[4] = {v.x, v.y, v.z, v.w};
    __nv_bfloat16 hh[4], ll[4];
    #pragma unroll
    for (int j = 0; j < 4; j++) {
        hh[j] = __float2bfloat16(f[j]);
        ll[j] = __float2bfloat16(f[j] - __bfloat162float(hh[j]));
    }
    *reinterpret_cast<uint2*>(h + i) = *reinterpret_cast<uint2*>(hh);
    *reinterpret_cast<uint2*>(l + i) = *reinterpret_cast<uint2*>(ll);
}

// ============================================================================
// bf16 [S,D] -> [D,S] transpose per batch; z = part*BB + b, part picks hi/lo
// ============================================================================
__global__ void transpose_kernel(const __nv_bfloat16* __restrict__ srcH,
                                 const __nv_bfloat16* __restrict__ srcL,
                                 __nv_bfloat16* __restrict__ dstH,
                                 __nv_bfloat16* __restrict__ dstL)
{
    __shared__ __nv_bfloat16 t[32][33];
    const int z = blockIdx.z;
    const int b = z & (BB - 1), part = z >> 2;
    const __nv_bfloat16* s = (part ? srcL : srcH) + (size_t)b * SS * DD;
    __nv_bfloat16* d = (part ? dstL : dstH) + (size_t)b * SS * DD;
    int d0 = blockIdx.x * 32, s0 = blockIdx.y * 32;
    #pragma unroll
    for (int i = threadIdx.y; i < 32; i += 8)
        t[i][threadIdx.x] = s[(size_t)(s0 + i) * DD + d0 + threadIdx.x];
    __syncthreads();
    #pragma unroll
    for (int i = threadIdx.y; i < 32; i += 8)
        d[(size_t)(d0 + i) * SS + s0 + threadIdx.x] = t[threadIdx.x][i];
}

// ============================================================================
// split-bf16 GEMM via mma.sync + cp.async 3-stage pipeline + register
// double-buffered fragments: C = sum_K (Ah+Al)(Bh+Bl)^T  (lo*lo dropped)
// A: [M,K] row-major bf16 hi/lo; B: [N,K] row-major bf16 hi/lo.
// 256 threads = 8 warps, warp tile 64x32 (warp grid 2m x 4n).
// ============================================================================
__global__ __launch_bounds__(256, 1)
void tc_gemm(const __nv_bfloat16* __restrict__ Ah, const __nv_bfloat16* __restrict__ Al, int lda,
             const __nv_bfloat16* __restrict__ Bh, const __nv_bfloat16* __restrict__ Bl, int ldb,
             const float* __restrict__ bias0, const float* __restrict__ bias1,
             const float* __restrict__ bias2, int biasByZ,
             float* __restrict__ Cf,
             __nv_bfloat16* __restrict__ Ch, __nv_bfloat16* __restrict__ Cl, int ldc,
             int K, long sA, long sB, long sC)
{
    extern __shared__ char smem[];
    const uint32_t sbase = smem_to_u32(smem);

    const int tid  = threadIdx.x;
    const int lane = tid & 31;
    const int wid  = tid >> 5;
    const int wm = (wid & 1) * 64;      // warp m offset in CTA tile
    const int wn = (wid >> 1) * 32;     // warp n offset
    const int rowBase = blockIdx.y * BM;
    const int colBase = blockIdx.x * BN;
    const int z = blockIdx.z;

    const float* bias = biasByZ ? ((z == 0) ? bias0 : (z == 1) ? bias1 : bias2) : bias0;

    const __nv_bfloat16* gsrc[4];
    gsrc[0] = Ah + (long)z * sA + (long)rowBase * lda;
    gsrc[1] = Al + (long)z * sA + (long)rowBase * lda;
    gsrc[2] = Bh + (long)z * sB + (long)colBase * ldb;
    gsrc[3] = Bl + (long)z * sB + (long)colBase * ldb;
    const int glds[4] = {lda, lda, ldb, ldb};

    const int r0f = tid >> 2;           // row for entry 0
    const int r1f = (tid + 256) >> 2;   // row for entry 1
    const int segf = tid & 3;

    float acc[4][4][4];
    #pragma unroll
    for (int mf = 0; mf < 4; mf++)
        #pragma unroll
        for (int nf = 0; nf < 4; nf++)
            #pragma unroll
            for (int j = 0; j < 4; j++) acc[mf][nf][j] = 0.f;

    // double-buffered register fragments
    uint32_t ahf[2][4][4], alf[2][4][4], bhf[2][4][2], blf[2][4][2];

    // precomputed lane components of ldsm addresses
    const uint32_t a_lane = (uint32_t)((wm + (lane & 15)) * 80 + ((lane >> 4) * 8) * 2);
    const uint32_t b_lane = (uint32_t)((wn + (lane & 7) + ((lane >> 4) & 1) * 8) * 80 +
                                       (((lane >> 3) & 1) * 8) * 2);

    auto issue_stage = [&](int stage, int k0) {
        const uint32_t st = sbase + (uint32_t)stage * STAGE_B;
        #pragma unroll
        for (int t = 0; t < 4; t++) {
            cp_async16(st + (uint32_t)(t * TILE_B + r0f * 80 + segf * 16),
                       gsrc[t] + (long)r0f * glds[t] + k0 + segf * 8);
            cp_async16(st + (uint32_t)(t * TILE_B + r1f * 80 + segf * 16),
                       gsrc[t] + (long)r1f * glds[t] + k0 + segf * 8);
        }
    };

    auto load_frags = [&](int fb, uint32_t st, int ks) {
        const uint32_t aoff = st + a_lane + (uint32_t)(ks * 32);
        #pragma unroll
        for (int mf = 0; mf < 4; mf++) {
            ldsm4(ahf[fb][mf], aoff + (uint32_t)(mf * 16 * 80));
            ldsm4(alf[fb][mf], aoff + TILE_B + (uint32_t)(mf * 16 * 80));
        }
        const uint32_t boff = st + 2 * TILE_B + b_lane + (uint32_t)(ks * 32);
        #pragma unroll
        for (int np = 0; np < 2; np++) {
            uint32_t r[4];
            ldsm4(r, boff + (uint32_t)(np * 16 * 80));
            bhf[fb][np * 2][0] = r[0]; bhf[fb][np * 2][1] = r[1];
            bhf[fb][np * 2 + 1][0] = r[2]; bhf[fb][np * 2 + 1][1] = r[3];
            ldsm4(r, boff + TILE_B + (uint32_t)(np * 16 * 80));
            blf[fb][np * 2][0] = r[0]; blf[fb][np * 2][1] = r[1];
            blf[fb][np * 2 + 1][0] = r[2]; blf[fb][np * 2 + 1][1] = r[3];
        }
    };

    auto do_mma = [&](int fb) {
        #pragma unroll
        for (int mf = 0; mf < 4; mf++)
            #pragma unroll
            for (int nf = 0; nf < 4; nf++) {
                mma_bf16(acc[mf][nf], ahf[fb][mf], bhf[fb][nf]);
                mma_bf16(acc[mf][nf], ahf[fb][mf], blf[fb][nf]);
                mma_bf16(acc[mf][nf], alf[fb][mf], bhf[fb][nf]);
            }
    };

    const int nch = K / BK;

    // prologue: stages 0,1 in flight; wait stage 0; start stage 2; frag(0,ks0)
    issue_stage(0, 0);  CP_COMMIT();
    issue_stage(1, BK); CP_COMMIT();
    CP_WAIT1();
    __syncthreads();
    if (nch > 2) issue_stage(2, 2 * BK);
    CP_COMMIT();
    load_frags(0, sbase, 0);

    for (int c = 0; c < nch; c++) {
        const uint32_t st = sbase + (uint32_t)(c % NSTAGE) * STAGE_B;
        load_frags(1, st, 1);           // overlap with do_mma(0) MMA issue
        do_mma(0);
        if (c + 1 < nch) {
            CP_WAIT1();                 // stage c+1 copies retired
            __syncthreads();            // all threads' copies visible; stage c%3 free
            if (c + 3 < nch) issue_stage((c + 3) % NSTAGE, (c + 3) * BK);
            CP_COMMIT();
            load_frags(0, sbase + (uint32_t)(((c + 1) % NSTAGE)) * STAGE_B, 0);
        }
        do_mma(1);
    }

    // ---- epilogue ----
    float* Cfb = Cf ? Cf + (long)z * sC : nullptr;
    __nv_bfloat16* Chb = Ch ? Ch + (long)z * sC : nullptr;
    __nv_bfloat16* Clb = Cl ? Cl + (long)z * sC : nullptr;

    #pragma unroll
    for (int mf = 0; mf < 4; mf++) {
        #pragma unroll
        for (int nf = 0; nf < 4; nf++) {
            const int r0 = rowBase + wm + mf * 16 + (lane >> 2);
            const int c0 = colBase + wn + nf * 8 + 2 * (lane & 3);
            const float b0 = bias ? bias[c0] : 0.f;
            const float b1 = bias ? bias[c0 + 1] : 0.f;
            const float v00 = acc[mf][nf][0] + b0;
            const float v01 = acc[mf][nf][1] + b1;
            const float v10 = acc[mf][nf][2] + b0;
            const float v11 = acc[mf][nf][3] + b1;
            if (Cfb) {
                *reinterpret_cast<float2*>(&Cfb[(long)r0 * ldc + c0]) = make_float2(v00, v01);
                *reinterpret_cast<float2*>(&Cfb[(long)(r0 + 8) * ldc + c0]) = make_float2(v10, v11);
            }
            if (Chb) {
                __nv_bfloat162 h2, l2;
                h2.x = __float2bfloat16(v00);
                h2.y = __float2bfloat16(v01);
                l2.x = __float2bfloat16(v00 - __bfloat162float(h2.x));
                l2.y = __float2bfloat16(v01 - __bfloat162float(h2.y));
                *reinterpret_cast<__nv_bfloat162*>(&Chb[(long)r0 * ldc + c0]) = h2;
                *reinterpret_cast<__nv_bfloat162*>(&Clb[(long)r0 * ldc + c0]) = l2;
                h2.x = __float2bfloat16(v10);
                h2.y = __float2bfloat16(v11);
                l2.x = __float2bfloat16(v10 - __bfloat162float(h2.x));
                l2.y = __float2bfloat16(v11 - __bfloat162float(h2.y));
                *reinterpret_cast<__nv_bfloat162*>(&Chb[(long)(r0 + 8) * ldc + c0]) = h2;
                *reinterpret_cast<__nv_bfloat162*>(&Clb[(long)(r0 + 8) * ldc + c0]) = l2;
            }
        }
    }
}

// ============================================================================
// fused combined + softmax (in-place fp32) + bf16 hi/lo output for attn@V
// combined = 0.7*score/128 + 0.3*(log(Z) - (Tq+Tk)/Z - 1.6e-7), Z = Sq_i + Sk_j
// ============================================================================
__global__ __launch_bounds__(256)
void softmax_kernel(float* __restrict__ attn,
                    __nv_bfloat16* __restrict__ ahi, __nv_bfloat16* __restrict__ alo,
                    const float* __restrict__ Sq, const float* __restrict__ Tq,
                    const float* __restrict__ Sk, const float* __restrict__ Tk)
{
    const int row = blockIdx.x;      // 0..4095
    const int b = row >> 10;
    float* a = attn + (size_t)row * SS;
    __nv_bfloat16* ah = ahi + (size_t)row * SS;
    __nv_bfloat16* al = alo + (size_t)row * SS;
    const float sq = Sq[row], tq = Tq[row];
    const float* skb = Sk + b * SS;
    const float* tkb = Tk + b * SS;
    const int tid = threadIdx.x;

    float c[4];
    float mx = -1e30f;
    #pragma unroll
    for (int u = 0; u < 4; u++) {
        int j = tid + u * 256;
        float Z = sq + skb[j];
        float ent = __logf(Z) - (tq + tkb[j]) / Z - 1.6e-7f;
        float v = 0.7f * (a[j] * (1.0f / 128.0f)) + 0.3f * ent;
        c[u] = v;
        mx = fmaxf(mx, v);
    }

    __shared__ float red[256];
    red[tid] = mx;
    __syncthreads();
    for (int s = 128; s > 0; s >>= 1) {
        if (tid < s) red[tid] = fmaxf(red[tid], red[tid + s]);
        __syncthreads();
    }
    mx = red[0];
    __syncthreads();

    float sum = 0.f;
    #pragma unroll
    for (int u = 0; u < 4; u++) {
        c[u] = __expf(c[u] - mx);
        sum += c[u];
    }
    red[tid] = sum;
    __syncthreads();
    for (int s = 128; s > 0; s >>= 1) {
        if (tid < s) red[tid] += red[tid + s];
        __syncthreads();
    }
    const float inv = 1.0f / red[0];

    #pragma unroll
    for (int u = 0; u < 4; u++) {
        int j = tid + u * 256;
        float f = c[u] * inv;
        a[j] = f;
        __nv_bfloat16 h = __float2bfloat16(f);
        ah[j] = h;
        al[j] = __float2bfloat16(f - __bfloat162float(h));
    }
}

// ============================================================================
// launch
// ============================================================================
extern "C" void kernel_launch(void* const* d_in, const int* in_sizes, int n_in,
                              void* d_out, int out_size)
{
    const float* query = (const float*)d_in[0];
    const float* key   = (const float*)d_in[1];
    const float* value = (const float*)d_in[2];
    const float* Wq = (const float*)d_in[3];
    const float* bq = (const float*)d_in[4];
    const float* Wk = (const float*)d_in[5];
    const float* bk = (const float*)d_in[6];
    const float* Wv = (const float*)d_in[7];
    const float* bv = (const float*)d_in[8];
    const float* Wo = (const float*)d_in[9];
    const float* bo = (const float*)d_in[10];

    float* out  = (float*)d_out;            // [B,S,D]
    float* attn = out + ELEMS;              // [B,S,S]

    cudaFuncSetAttribute(tc_gemm, cudaFuncAttributeMaxDynamicSharedMemorySize, SMEM_REQ);

    auto sym = [](const void* s) {
        void* p = nullptr;
        cudaGetSymbolAddress(&p, s);
        return p;
    };
    __nv_bfloat16* Xh  = (__nv_bfloat16*)sym(g_Xh);  __nv_bfloat16* Xl  = (__nv_bfloat16*)sym(g_Xl);
    __nv_bfloat16* Wh  = (__nv_bfloat16*)sym(g_Wh);  __nv_bfloat16* Wl  = (__nv_bfloat16*)sym(g_Wl);
    __nv_bfloat16* Ph  = (__nv_bfloat16*)sym(g_Ph);  __nv_bfloat16* Pl  = (__nv_bfloat16*)sym(g_Pl);
    __nv_bfloat16* Vth = (__nv_bfloat16*)sym(g_Vth); __nv_bfloat16* Vtl = (__nv_bfloat16*)sym(g_Vtl);
    __nv_bfloat16* Ahh = (__nv_bfloat16*)sym(g_Ah);  __nv_bfloat16* All = (__nv_bfloat16*)sym(g_Al);
    __nv_bfloat16* AVh = (__nv_bfloat16*)sym(g_AVh); __nv_bfloat16* AVl = (__nv_bfloat16*)sym(g_AVl);
    float* pSq = (float*)sym(g_Sq); float* pTq = (float*)sym(g_Tq);
    float* pSk = (float*)sym(g_Sk); float* pTk = (float*)sym(g_Tk);

    const int NE = (int)ELEMS;

    // 1) entropy stats + fused input/weight splits
    stats_kernel<<<BS / 256, 256>>>(query, key, pSq, pTq, pSk, pTk);
    convert_kernel<<<dim3(NE / 1024, 1, 3), 256>>>(query, key, value, value, Xh, Xl, NE);
    convert_kernel<<<dim3(NW / 1024, 1, 4), 256>>>(Wq, Wk, Wv, Wo, Wh, Wl, NW);

    // 2) fused Q/K/V projections: X[z] @ W[z]^T + b[z]   (z = 0,1,2)
    dim3 gp(DD / BN, BS / BM, 3);
    tc_gemm<<<gp, 256, SMEM_REQ>>>(Xh, Xl, DD, Wh, Wl, DD, bq, bk, bv, 1,
                                   nullptr, Ph, Pl, DD, DD,
                                   (long)ELEMS, (long)NW, (long)ELEMS);

    // 3) V^T hi+lo in one launch ([N=d, K=t] row-major for attn@V)
    dim3 gt(DD / 32, SS / 32, 2 * BB);
    transpose_kernel<<<gt, dim3(32, 8)>>>(Ph + 2 * ELEMS, Pl + 2 * ELEMS, Vth, Vtl);

    // 4) scores S = Q @ K^T per batch -> fp32 into attn buffer
    dim3 gs(SS / BN, SS / BM, BB);
    tc_gemm<<<gs, 256, SMEM_REQ>>>(Ph, Pl, DD, Ph + ELEMS, Pl + ELEMS, DD,
                                   nullptr, nullptr, nullptr, 0,
                                   attn, nullptr, nullptr, SS,
                                   DD, (long)SS * DD, (long)SS * DD, (long)SS * SS);

    // 5) fused combined + softmax (in place) + bf16 split attn
    softmax_kernel<<<BS, 256>>>(attn, Ahh, All, pSq, pTq, pSk, pTk);

    // 6) AV = attn @ V per batch (B = V^T, K-major over t)
    tc_gemm<<<gs, 256, SMEM_REQ>>>(Ahh, All, SS, Vth, Vtl, SS,
                                   nullptr, nullptr, nullptr, 0,
                                   nullptr, AVh, AVl, DD,
                                   SS, (long)SS * SS, (long)SS * DD, (long)SS * DD);

    // 7) output = AV @ Wo^T + bo
    dim3 go(DD / BN, BS / BM, 1);
    tc_gemm<<<go, 256, SMEM_REQ>>>(AVh, AVl, DD, Wh + 3 * (size_t)NW, Wl + 3 * (size_t)NW, DD,
                                   bo, nullptr, nullptr, 0,
                                   out, nullptr, nullptr, DD, DD, 0, 0, 0);
}

// round 13
// speedup vs baseline: 1.0475x; 1.0475x over previous
#include <cuda_runtime.h>
#include <cuda_bf16.h>
#include <cstdint>
#include <math.h>

// Problem constants
#define BB 4
#define SS 1024
#define DD 1024
#define BS (BB*SS)                  // 4096 rows total
#define ELEMS ((size_t)BB*SS*DD)    // 4194304  (== B*S*S too)
#define NW (DD*DD)

// ============================================================================
// GEMM tiling: CTA 128x128x32, 512 threads = 16 warps, warp tile 32x32
// ============================================================================
#define BM 128
#define BN 128
#define BK 32
#define ASTRIDE 40                      // bf16 elems per smem row (80 bytes)
#define TILE_B (128*ASTRIDE*2)          // 10240 bytes per tile (128 rows x 80B)
#define STAGE_B (4*TILE_B)              // Ah, Al, Bh, Bl = 40960 B
#define NSTAGE 3
#define SMEM_REQ (NSTAGE*STAGE_B)       // 122880 B

__device__ __forceinline__ uint32_t smem_to_u32(const void* smem_ptr) {
    uint32_t addr;
    asm("{ .reg .u64 tmp; cvta.to.shared.u64 tmp, %1; cvt.u32.u64 %0, tmp; }"
        : "=r"(addr) : "l"(smem_ptr));
    return addr;
}
__device__ __forceinline__ void ldsm4(uint32_t* r, uint32_t addr) {
    asm volatile("ldmatrix.sync.aligned.m8n8.x4.shared.b16 {%0,%1,%2,%3}, [%4];"
                 : "=r"(r[0]), "=r"(r[1]), "=r"(r[2]), "=r"(r[3]) : "r"(addr));
}
__device__ __forceinline__ void mma_bf16(float* c, const uint32_t* a, const uint32_t* b) {
    asm volatile(
        "mma.sync.aligned.m16n8k16.row.col.f32.bf16.bf16.f32 "
        "{%0,%1,%2,%3}, {%4,%5,%6,%7}, {%8,%9}, {%0,%1,%2,%3};"
        : "+f"(c[0]), "+f"(c[1]), "+f"(c[2]), "+f"(c[3])
        : "r"(a[0]), "r"(a[1]), "r"(a[2]), "r"(a[3]), "r"(b[0]), "r"(b[1]));
}
__device__ __forceinline__ void cp_async16(uint32_t dst, const void* src) {
    asm volatile("cp.async.cg.shared.global [%0], [%1], 16;" :: "r"(dst), "l"(src));
}
#define CP_COMMIT() asm volatile("cp.async.commit_group;" ::: "memory")
#define CP_WAIT1()  asm volatile("cp.async.wait_group 1;" ::: "memory")

// ============================================================================
// Scratch (no allocation allowed) — merged contiguous regions for z-batching
// ============================================================================
__device__ __nv_bfloat16 g_Xh[3*ELEMS], g_Xl[3*ELEMS];   // q,k,v inputs split
__device__ __nv_bfloat16 g_Wh[4*NW],    g_Wl[4*NW];      // Wq,Wk,Wv,Wo split
__device__ __nv_bfloat16 g_Ph[3*ELEMS], g_Pl[3*ELEMS];   // Q,K,V projections split
__device__ __nv_bfloat16 g_Vth[ELEMS],  g_Vtl[ELEMS];    // V^T split
__device__ __nv_bfloat16 g_Ah[ELEMS],   g_Al[ELEMS];     // attn split
__device__ __nv_bfloat16 g_AVh[ELEMS],  g_AVl[ELEMS];    // attn@V split
__device__ float g_Sq[BS], g_Tq[BS], g_Sk[BS], g_Tk[BS];

// ============================================================================
// Entropy stats: Sq[r]=sum exp(tanh(q[r,m])), Tq[r]=sum x*exp(x), m<8
// ============================================================================
__global__ void stats_kernel(const float* __restrict__ q, const float* __restrict__ k,
                             float* __restrict__ Sq, float* __restrict__ Tq,
                             float* __restrict__ Sk, float* __restrict__ Tk)
{
    int r = blockIdx.x * blockDim.x + threadIdx.x;
    if (r >= BS) return;
    float s = 0.f, t = 0.f;
    #pragma unroll
    for (int m = 0; m < 8; m++) {
        float x = tanhf(q[(size_t)r * DD + m]);
        float e = expf(x);
        s += e; t += x * e;
    }
    Sq[r] = s; Tq[r] = t;
    s = 0.f; t = 0.f;
    #pragma unroll
    for (int m = 0; m < 8; m++) {
        float x = tanhf(k[(size_t)r * DD + m]);
        float e = expf(x);
        s += e; t += x * e;
    }
    Sk[r] = s; Tk[r] = t;
}

// ============================================================================
// fp32 -> (hi, lo) bf16 split; z selects one of up to 4 sources
// ============================================================================
__global__ void convert_kernel(const float* __restrict__ x0, const float* __restrict__ x1,
                               const float* __restrict__ x2, const float* __restrict__ x3,
                               __nv_bfloat16* __restrict__ hi,
                               __nv_bfloat16* __restrict__ lo, int n)
{
    const int z = blockIdx.z;
    const float* x = (z == 0) ? x0 : (z == 1) ? x1 : (z == 2) ? x2 : x3;
    __nv_bfloat16* h = hi + (size_t)z * n;
    __nv_bfloat16* l = lo + (size_t)z * n;
    int i = (blockIdx.x * blockDim.x + threadIdx.x) * 4;
    if (i >= n) return;
    float4 v = *reinterpret_cast<const float4*>(x + i);
    float f[4] = {v.x, v.y, v.z, v.w};
    __nv_bfloat16 hh[4], ll[4];
    #pragma unroll
    for (int j = 0; j < 4; j++) {
        hh[j] = __float2bfloat16(f[j]);
        ll[j] = __float2bfloat16(f[j] - __bfloat162float(hh[j]));
    }
    *reinterpret_cast<uint2*>(h + i) = *reinterpret_cast<uint2*>(hh);
    *reinterpret_cast<uint2*>(l + i) = *reinterpret_cast<uint2*>(ll);
}

// ============================================================================
// bf16 [S,D] -> [D,S] transpose per batch; z = part*BB + b, part picks hi/lo
// ============================================================================
__global__ void transpose_kernel(const __nv_bfloat16* __restrict__ srcH,
                                 const __nv_bfloat16* __restrict__ srcL,
                                 __nv_bfloat16* __restrict__ dstH,
                                 __nv_bfloat16* __restrict__ dstL)
{
    __shared__ __nv_bfloat16 t[32][33];
    const int z = blockIdx.z;
    const int b = z & (BB - 1), part = z >> 2;
    const __nv_bfloat16* s = (part ? srcL : srcH) + (size_t)b * SS * DD;
    __nv_bfloat16* d = (part ? dstL : dstH) + (size_t)b * SS * DD;
    int d0 = blockIdx.x * 32, s0 = blockIdx.y * 32;
    #pragma unroll
    for (int i = threadIdx.y; i < 32; i += 8)
        t[i][threadIdx.x] = s[(size_t)(s0 + i) * DD + d0 + threadIdx.x];
    __syncthreads();
    #pragma unroll
    for (int i = threadIdx.y; i < 32; i += 8)
        d[(size_t)(d0 + i) * SS + s0 + threadIdx.x] = t[threadIdx.x][i];
}

// ============================================================================
// split-bf16 GEMM via mma.sync + cp.async 3-stage pipeline:
//   C[M,N] = sum_K (Ah+Al)(Bh+Bl)^T  (lo*lo dropped)
// A: [M,K] row-major bf16 hi/lo; B: [N,K] row-major bf16 hi/lo.
// 512 threads = 16 warps, warp grid 4m x 4n, warp tile 32x32.
// ============================================================================
__global__ __launch_bounds__(512, 1)
void tc_gemm(const __nv_bfloat16* __restrict__ Ah, const __nv_bfloat16* __restrict__ Al, int lda,
             const __nv_bfloat16* __restrict__ Bh, const __nv_bfloat16* __restrict__ Bl, int ldb,
             const float* __restrict__ bias0, const float* __restrict__ bias1,
             const float* __restrict__ bias2, int biasByZ,
             float* __restrict__ Cf,
             __nv_bfloat16* __restrict__ Ch, __nv_bfloat16* __restrict__ Cl, int ldc,
             int K, long sA, long sB, long sC)
{
    extern __shared__ char smem[];
    const uint32_t sbase = smem_to_u32(smem);

    const int tid  = threadIdx.x;
    const int lane = tid & 31;
    const int wid  = tid >> 5;
    const int wm = (wid & 3) * 32;      // warp m offset in CTA tile
    const int wn = (wid >> 2) * 32;     // warp n offset
    const int rowBase = blockIdx.y * BM;
    const int colBase = blockIdx.x * BN;
    const int z = blockIdx.z;

    const float* bias = biasByZ ? ((z == 0) ? bias0 : (z == 1) ? bias1 : bias2) : bias0;

    const __nv_bfloat16* gsrc[4];
    gsrc[0] = Ah + (long)z * sA + (long)rowBase * lda;
    gsrc[1] = Al + (long)z * sA + (long)rowBase * lda;
    gsrc[2] = Bh + (long)z * sB + (long)colBase * ldb;
    gsrc[3] = Bl + (long)z * sB + (long)colBase * ldb;
    const int glds[4] = {lda, lda, ldb, ldb};

    const int r0f = tid >> 2;           // 0..127 (each thread: one 16B seg per tile)
    const int segf = tid & 3;

    float acc[2][4][4];
    #pragma unroll
    for (int mf = 0; mf < 2; mf++)
        #pragma unroll
        for (int nf = 0; nf < 4; nf++)
            #pragma unroll
            for (int j = 0; j < 4; j++) acc[mf][nf][j] = 0.f;

    // lane components of ldsm addresses
    const uint32_t a_lane = (uint32_t)((wm + (lane & 15)) * 80 + ((lane >> 4) * 8) * 2);
    const uint32_t b_lane = (uint32_t)((wn + (lane & 7) + ((lane >> 4) & 1) * 8) * 80 +
                                       (((lane >> 3) & 1) * 8) * 2);

    auto issue_stage = [&](int stage, int k0) {
        const uint32_t st = sbase + (uint32_t)stage * STAGE_B;
        #pragma unroll
        for (int t = 0; t < 4; t++) {
            cp_async16(st + (uint32_t)(t * TILE_B + r0f * 80 + segf * 16),
                       gsrc[t] + (long)r0f * glds[t] + k0 + segf * 8);
        }
    };

    // prologue: stages 0,1 in flight; wait stage 0; start stage 2
    issue_stage(0, 0);  CP_COMMIT();
    issue_stage(1, BK); CP_COMMIT();
    CP_WAIT1();
    __syncthreads();

    const int nch = K / BK;
    if (nch > 2) issue_stage(2, 2 * BK);
    CP_COMMIT();

    for (int c = 0; c < nch; c++) {
        const uint32_t st = sbase + (uint32_t)(c % NSTAGE) * STAGE_B;

        #pragma unroll
        for (int ks = 0; ks < 2; ks++) {
            uint32_t ah[2][4], al[2][4], bh[4][2], bl[4][2];
            const uint32_t aoff = st + a_lane + (uint32_t)(ks * 32);
            #pragma unroll
            for (int mf = 0; mf < 2; mf++) {
                ldsm4(ah[mf], aoff + (uint32_t)(mf * 16 * 80));
                ldsm4(al[mf], aoff + TILE_B + (uint32_t)(mf * 16 * 80));
            }
            const uint32_t boff = st + 2 * TILE_B + b_lane + (uint32_t)(ks * 32);
            #pragma unroll
            for (int np = 0; np < 2; np++) {
                uint32_t r[4];
                ldsm4(r, boff + (uint32_t)(np * 16 * 80));
                bh[np * 2][0] = r[0]; bh[np * 2][1] = r[1];
                bh[np * 2 + 1][0] = r[2]; bh[np * 2 + 1][1] = r[3];
                ldsm4(r, boff + TILE_B + (uint32_t)(np * 16 * 80));
                bl[np * 2][0] = r[0]; bl[np * 2][1] = r[1];
                bl[np * 2 + 1][0] = r[2]; bl[np * 2 + 1][1] = r[3];
            }
            #pragma unroll
            for (int mf = 0; mf < 2; mf++)
                #pragma unroll
                for (int nf = 0; nf < 4; nf++) {
                    mma_bf16(acc[mf][nf], ah[mf], bh[nf]);
                    mma_bf16(acc[mf][nf], ah[mf], bl[nf]);
                    mma_bf16(acc[mf][nf], al[mf], bh[nf]);
                }
        }

        if (c + 1 < nch) {
            CP_WAIT1();                 // stage c+1 copies retired
            __syncthreads();            // visible to all; stage c%3 free to refill
            if (c + 3 < nch) issue_stage((c + 3) % NSTAGE, (c + 3) * BK);
            CP_COMMIT();
        }
    }

    // ---- epilogue ----
    float* Cfb = Cf ? Cf + (long)z * sC : nullptr;
    __nv_bfloat16* Chb = Ch ? Ch + (long)z * sC : nullptr;
    __nv_bfloat16* Clb = Cl ? Cl + (long)z * sC : nullptr;

    #pragma unroll
    for (int mf = 0; mf < 2; mf++) {
        #pragma unroll
        for (int nf = 0; nf < 4; nf++) {
            const int r0 = rowBase + wm + mf * 16 + (lane >> 2);
            const int c0 = colBase + wn + nf * 8 + 2 * (lane & 3);
            const float b0 = bias ? bias[c0] : 0.f;
            const float b1 = bias ? bias[c0 + 1] : 0.f;
            const float v00 = acc[mf][nf][0] + b0;
            const float v01 = acc[mf][nf][1] + b1;
            const float v10 = acc[mf][nf][2] + b0;
            const float v11 = acc[mf][nf][3] + b1;
            if (Cfb) {
                *reinterpret_cast<float2*>(&Cfb[(long)r0 * ldc + c0]) = make_float2(v00, v01);
                *reinterpret_cast<float2*>(&Cfb[(long)(r0 + 8) * ldc + c0]) = make_float2(v10, v11);
            }
            if (Chb) {
                __nv_bfloat162 h2, l2;
                h2.x = __float2bfloat16(v00);
                h2.y = __float2bfloat16(v01);
                l2.x = __float2bfloat16(v00 - __bfloat162float(h2.x));
                l2.y = __float2bfloat16(v01 - __bfloat162float(h2.y));
                *reinterpret_cast<__nv_bfloat162*>(&Chb[(long)r0 * ldc + c0]) = h2;
                *reinterpret_cast<__nv_bfloat162*>(&Clb[(long)r0 * ldc + c0]) = l2;
                h2.x = __float2bfloat16(v10);
                h2.y = __float2bfloat16(v11);
                l2.x = __float2bfloat16(v10 - __bfloat162float(h2.x));
                l2.y = __float2bfloat16(v11 - __bfloat162float(h2.y));
                *reinterpret_cast<__nv_bfloat162*>(&Chb[(long)(r0 + 8) * ldc + c0]) = h2;
                *reinterpret_cast<__nv_bfloat162*>(&Clb[(long)(r0 + 8) * ldc + c0]) = l2;
            }
        }
    }
}

// ============================================================================
// fused combined + softmax (in-place fp32) + bf16 hi/lo output for attn@V
// combined = 0.7*score/128 + 0.3*(log(Z) - (Tq+Tk)/Z - 1.6e-7), Z = Sq_i + Sk_j
// ============================================================================
__global__ __launch_bounds__(256)
void softmax_kernel(float* __restrict__ attn,
                    __nv_bfloat16* __restrict__ ahi, __nv_bfloat16* __restrict__ alo,
                    const float* __restrict__ Sq, const float* __restrict__ Tq,
                    const float* __restrict__ Sk, const float* __restrict__ Tk)
{
    const int row = blockIdx.x;      // 0..4095
    const int b = row >> 10;
    float* a = attn + (size_t)row * SS;
    __nv_bfloat16* ah = ahi + (size_t)row * SS;
    __nv_bfloat16* al = alo + (size_t)row * SS;
    const float sq = Sq[row], tq = Tq[row];
    const float* skb = Sk + b * SS;
    const float* tkb = Tk + b * SS;
    const int tid = threadIdx.x;

    float c[4];
    float mx = -1e30f;
    #pragma unroll
    for (int u = 0; u < 4; u++) {
        int j = tid + u * 256;
        float Z = sq + skb[j];
        float ent = __logf(Z) - (tq + tkb[j]) / Z - 1.6e-7f;
        float v = 0.7f * (a[j] * (1.0f / 128.0f)) + 0.3f * ent;
        c[u] = v;
        mx = fmaxf(mx, v);
    }

    __shared__ float red[256];
    red[tid] = mx;
    __syncthreads();
    for (int s = 128; s > 0; s >>= 1) {
        if (tid < s) red[tid] = fmaxf(red[tid], red[tid + s]);
        __syncthreads();
    }
    mx = red[0];
    __syncthreads();

    float sum = 0.f;
    #pragma unroll
    for (int u = 0; u < 4; u++) {
        c[u] = __expf(c[u] - mx);
        sum += c[u];
    }
    red[tid] = sum;
    __syncthreads();
    for (int s = 128; s > 0; s >>= 1) {
        if (tid < s) red[tid] += red[tid + s];
        __syncthreads();
    }
    const float inv = 1.0f / red[0];

    #pragma unroll
    for (int u = 0; u < 4; u++) {
        int j = tid + u * 256;
        float f = c[u] * inv;
        a[j] = f;
        __nv_bfloat16 h = __float2bfloat16(f);
        ah[j] = h;
        al[j] = __float2bfloat16(f - __bfloat162float(h));
    }
}

// ============================================================================
// launch
// ============================================================================
extern "C" void kernel_launch(void* const* d_in, const int* in_sizes, int n_in,
                              void* d_out, int out_size)
{
    const float* query = (const float*)d_in[0];
    const float* key   = (const float*)d_in[1];
    const float* value = (const float*)d_in[2];
    const float* Wq = (const float*)d_in[3];
    const float* bq = (const float*)d_in[4];
    const float* Wk = (const float*)d_in[5];
    const float* bk = (const float*)d_in[6];
    const float* Wv = (const float*)d_in[7];
    const float* bv = (const float*)d_in[8];
    const float* Wo = (const float*)d_in[9];
    const float* bo = (const float*)d_in[10];

    float* out  = (float*)d_out;            // [B,S,D]
    float* attn = out + ELEMS;              // [B,S,S]

    cudaFuncSetAttribute(tc_gemm, cudaFuncAttributeMaxDynamicSharedMemorySize, SMEM_REQ);

    auto sym = [](const void* s) {
        void* p = nullptr;
        cudaGetSymbolAddress(&p, s);
        return p;
    };
    __nv_bfloat16* Xh  = (__nv_bfloat16*)sym(g_Xh);  __nv_bfloat16* Xl  = (__nv_bfloat16*)sym(g_Xl);
    __nv_bfloat16* Wh  = (__nv_bfloat16*)sym(g_Wh);  __nv_bfloat16* Wl  = (__nv_bfloat16*)sym(g_Wl);
    __nv_bfloat16* Ph  = (__nv_bfloat16*)sym(g_Ph);  __nv_bfloat16* Pl  = (__nv_bfloat16*)sym(g_Pl);
    __nv_bfloat16* Vth = (__nv_bfloat16*)sym(g_Vth); __nv_bfloat16* Vtl = (__nv_bfloat16*)sym(g_Vtl);
    __nv_bfloat16* Ahh = (__nv_bfloat16*)sym(g_Ah);  __nv_bfloat16* All = (__nv_bfloat16*)sym(g_Al);
    __nv_bfloat16* AVh = (__nv_bfloat16*)sym(g_AVh); __nv_bfloat16* AVl = (__nv_bfloat16*)sym(g_AVl);
    float* pSq = (float*)sym(g_Sq); float* pTq = (float*)sym(g_Tq);
    float* pSk = (float*)sym(g_Sk); float* pTk = (float*)sym(g_Tk);

    const int NE = (int)ELEMS;

    // 1) entropy stats + fused input/weight splits
    stats_kernel<<<BS / 256, 256>>>(query, key, pSq, pTq, pSk, pTk);
    convert_kernel<<<dim3(NE / 1024, 1, 3), 256>>>(query, key, value, value, Xh, Xl, NE);
    convert_kernel<<<dim3(NW / 1024, 1, 4), 256>>>(Wq, Wk, Wv, Wo, Wh, Wl, NW);

    // 2) fused Q/K/V projections: X[z] @ W[z]^T + b[z]   (z = 0,1,2)
    dim3 gp(DD / BN, BS / BM, 3);
    tc_gemm<<<gp, 512, SMEM_REQ>>>(Xh, Xl, DD, Wh, Wl, DD, bq, bk, bv, 1,
                                   nullptr, Ph, Pl, DD, DD,
                                   (long)ELEMS, (long)NW, (long)ELEMS);

    // 3) V^T hi+lo in one launch ([N=d, K=t] row-major for attn@V)
    dim3 gt(DD / 32, SS / 32, 2 * BB);
    transpose_kernel<<<gt, dim3(32, 8)>>>(Ph + 2 * ELEMS, Pl + 2 * ELEMS, Vth, Vtl);

    // 4) scores S = Q @ K^T per batch -> fp32 into attn buffer
    dim3 gs(SS / BN, SS / BM, BB);
    tc_gemm<<<gs, 512, SMEM_REQ>>>(Ph, Pl, DD, Ph + ELEMS, Pl + ELEMS, DD,
                                   nullptr, nullptr, nullptr, 0,
                                   attn, nullptr, nullptr, SS,
                                   DD, (long)SS * DD, (long)SS * DD, (long)SS * SS);

    // 5) fused combined + softmax (in place) + bf16 split attn
    softmax_kernel<<<BS, 256>>>(attn, Ahh, All, pSq, pTq, pSk, pTk);

    // 6) AV = attn @ V per batch (B = V^T, K-major over t)
    tc_gemm<<<gs, 512, SMEM_REQ>>>(Ahh, All, SS, Vth, Vtl, SS,
                                   nullptr, nullptr, nullptr, 0,
                                   nullptr, AVh, AVl, DD,
                                   SS, (long)SS * SS, (long)SS * DD, (long)SS * DD);

    // 7) output = AV @ Wo^T + bo
    dim3 go(DD / BN, BS / BM, 1);
    tc_gemm<<<go, 512, SMEM_REQ>>>(AVh, AVl, DD, Wh + 3 * (size_t)NW, Wl + 3 * (size_t)NW, DD,
                                   bo, nullptr, nullptr, 0,
                                   out, nullptr, nullptr, DD, DD, 0, 0, 0);
}

// round 16
// speedup vs baseline: 1.0481x; 1.0006x over previous
#include <cuda_runtime.h>
#include <cuda_bf16.h>
#include <cstdint>
#include <math.h>

// Problem constants
#define BB 4
#define SS 1024
#define DD 1024
#define BS (BB*SS)                  // 4096 rows total
#define ELEMS ((size_t)BB*SS*DD)    // 4194304  (== B*S*S too)
#define NW (DD*DD)

// ============================================================================
// GEMM tiling: CTA 128x128x32, 512 threads = 16 warps, warp tile 32x32
// ============================================================================
#define BM 128
#define BN 128
#define BK 32
#define ASTRIDE 40                      // bf16 elems per smem row (80 bytes)
#define TILE_B (128*ASTRIDE*2)          // 10240 bytes per tile (128 rows x 80B)
#define STAGE_B (4*TILE_B)              // Ah, Al, Bh, Bl = 40960 B
#define NSTAGE 3
#define SMEM_REQ (NSTAGE*STAGE_B)       // 122880 B

__device__ __forceinline__ uint32_t smem_to_u32(const void* smem_ptr) {
    uint32_t addr;
    asm("{ .reg .u64 tmp; cvta.to.shared.u64 tmp, %1; cvt.u32.u64 %0, tmp; }"
        : "=r"(addr) : "l"(smem_ptr));
    return addr;
}
__device__ __forceinline__ void ldsm4(uint32_t* r, uint32_t addr) {
    asm volatile("ldmatrix.sync.aligned.m8n8.x4.shared.b16 {%0,%1,%2,%3}, [%4];"
                 : "=r"(r[0]), "=r"(r[1]), "=r"(r[2]), "=r"(r[3]) : "r"(addr));
}
__device__ __forceinline__ void mma_bf16(float* c, const uint32_t* a, const uint32_t* b) {
    asm volatile(
        "mma.sync.aligned.m16n8k16.row.col.f32.bf16.bf16.f32 "
        "{%0,%1,%2,%3}, {%4,%5,%6,%7}, {%8,%9}, {%0,%1,%2,%3};"
        : "+f"(c[0]), "+f"(c[1]), "+f"(c[2]), "+f"(c[3])
        : "r"(a[0]), "r"(a[1]), "r"(a[2]), "r"(a[3]), "r"(b[0]), "r"(b[1]));
}
__device__ __forceinline__ void cp_async16(uint32_t dst, const void* src) {
    asm volatile("cp.async.cg.shared.global [%0], [%1], 16;" :: "r"(dst), "l"(src));
}
#define CP_COMMIT() asm volatile("cp.async.commit_group;" ::: "memory")
#define CP_WAIT1()  asm volatile("cp.async.wait_group 1;" ::: "memory")

// ============================================================================
// Scratch (no allocation allowed) — merged contiguous regions for z-batching
// ============================================================================
__device__ __nv_bfloat16 g_Xh[3*ELEMS], g_Xl[3*ELEMS];   // q,k,v inputs split
__device__ __nv_bfloat16 g_Wh[4*NW],    g_Wl[4*NW];      // Wq,Wk,Wv,Wo split
__device__ __nv_bfloat16 g_Ph[3*ELEMS], g_Pl[3*ELEMS];   // Q,K,V projections split
__device__ __nv_bfloat16 g_Vth[ELEMS],  g_Vtl[ELEMS];    // V^T split
__device__ __nv_bfloat16 g_Ah[ELEMS],   g_Al[ELEMS];     // attn split
__device__ __nv_bfloat16 g_AVh[ELEMS],  g_AVl[ELEMS];    // attn@V split
__device__ float g_Sq[BS], g_Tq[BS], g_Sk[BS], g_Tk[BS];

// ============================================================================
// Entropy stats: Sq[r]=sum exp(tanh(q[r,m])), Tq[r]=sum x*exp(x), m<8
// ============================================================================
__global__ void stats_kernel(const float* __restrict__ q, const float* __restrict__ k,
                             float* __restrict__ Sq, float* __restrict__ Tq,
                             float* __restrict__ Sk, float* __restrict__ Tk)
{
    int r = blockIdx.x * blockDim.x + threadIdx.x;
    if (r >= BS) return;
    float s = 0.f, t = 0.f;
    #pragma unroll
    for (int m = 0; m < 8; m++) {
        float x = tanhf(q[(size_t)r * DD + m]);
        float e = expf(x);
        s += e; t += x * e;
    }
    Sq[r] = s; Tq[r] = t;
    s = 0.f; t = 0.f;
    #pragma unroll
    for (int m = 0; m < 8; m++) {
        float x = tanhf(k[(size_t)r * DD + m]);
        float e = expf(x);
        s += e; t += x * e;
    }
    Sk[r] = s; Tk[r] = t;
}

// ============================================================================
// fp32 -> (hi, lo) bf16 split; z selects one of up to 4 sources
// ============================================================================
__global__ void convert_kernel(const float* __restrict__ x0, const float* __restrict__ x1,
                               const float* __restrict__ x2, const float* __restrict__ x3,
                               __nv_bfloat16* __restrict__ hi,
                               __nv_bfloat16* __restrict__ lo, int n)
{
    const int z = blockIdx.z;
    const float* x = (z == 0) ? x0 : (z == 1) ? x1 : (z == 2) ? x2 : x3;
    __nv_bfloat16* h = hi + (size_t)z * n;
    __nv_bfloat16* l = lo + (size_t)z * n;
    int i = (blockIdx.x * blockDim.x + threadIdx.x) * 4;
    if (i >= n) return;
    float4 v = *reinterpret_cast<const float4*>(x + i);
    float f[4] = {v.x, v.y, v.z, v.w};
    __nv_bfloat16 hh[4], ll[4];
    #pragma unroll
    for (int j = 0; j < 4; j++) {
        hh[j] = __float2bfloat16(f[j]);
        ll[j] = __float2bfloat16(f[j] - __bfloat162float(hh[j]));
    }
    *reinterpret_cast<uint2*>(h + i) = *reinterpret_cast<uint2*>(hh);
    *reinterpret_cast<uint2*>(l + i) = *reinterpret_cast<uint2*>(ll);
}

// ============================================================================
// bf16 [S,D] -> [D,S] transpose per batch; z = part*BB + b, part picks hi/lo
// ============================================================================
__global__ void transpose_kernel(const __nv_bfloat16* __restrict__ srcH,
                                 const __nv_bfloat16* __restrict__ srcL,
                                 __nv_bfloat16* __restrict__ dstH,
                                 __nv_bfloat16* __restrict__ dstL)
{
    __shared__ __nv_bfloat16 t[32][33];
    const int z = blockIdx.z;
    const int b = z & (BB - 1), part = z >> 2;
    const __nv_bfloat16* s = (part ? srcL : srcH) + (size_t)b * SS * DD;
    __nv_bfloat16* d = (part ? dstL : dstH) + (size_t)b * SS * DD;
    int d0 = blockIdx.x * 32, s0 = blockIdx.y * 32;
    #pragma unroll
    for (int i = threadIdx.y; i < 32; i += 8)
        t[i][threadIdx.x] = s[(size_t)(s0 + i) * DD + d0 + threadIdx.x];
    __syncthreads();
    #pragma unroll
    for (int i = threadIdx.y; i < 32; i += 8)
        d[(size_t)(d0 + i) * SS + s0 + threadIdx.x] = t[threadIdx.x][i];
}

// ============================================================================
// split-bf16 GEMM via mma.sync + cp.async 3-stage pipeline:
//   C[M,N] = sum_K (Ah+Al)(Bh+Bl)^T  (lo*lo dropped)
// A: [M,K] row-major bf16 hi/lo; B: [N,K] row-major bf16 hi/lo.
// 512 threads = 16 warps, warp grid 4m x 4n, warp tile 32x32.
// MMA issue order is TERM-OUTERMOST: all hh, then all hl, then all lh —
// same-accumulator reuse distance 8 instructions (kills RAW-latency chains).
// ============================================================================
__global__ __launch_bounds__(512, 1)
void tc_gemm(const __nv_bfloat16* __restrict__ Ah, const __nv_bfloat16* __restrict__ Al, int lda,
             const __nv_bfloat16* __restrict__ Bh, const __nv_bfloat16* __restrict__ Bl, int ldb,
             const float* __restrict__ bias0, const float* __restrict__ bias1,
             const float* __restrict__ bias2, int biasByZ,
             float* __restrict__ Cf,
             __nv_bfloat16* __restrict__ Ch, __nv_bfloat16* __restrict__ Cl, int ldc,
             int K, long sA, long sB, long sC)
{
    extern __shared__ char smem[];
    const uint32_t sbase = smem_to_u32(smem);

    const int tid  = threadIdx.x;
    const int lane = tid & 31;
    const int wid  = tid >> 5;
    const int wm = (wid & 3) * 32;      // warp m offset in CTA tile
    const int wn = (wid >> 2) * 32;     // warp n offset
    const int rowBase = blockIdx.y * BM;
    const int colBase = blockIdx.x * BN;
    const int z = blockIdx.z;

    const float* bias = biasByZ ? ((z == 0) ? bias0 : (z == 1) ? bias1 : bias2) : bias0;

    const __nv_bfloat16* gsrc[4];
    gsrc[0] = Ah + (long)z * sA + (long)rowBase * lda;
    gsrc[1] = Al + (long)z * sA + (long)rowBase * lda;
    gsrc[2] = Bh + (long)z * sB + (long)colBase * ldb;
    gsrc[3] = Bl + (long)z * sB + (long)colBase * ldb;
    const int glds[4] = {lda, lda, ldb, ldb};

    const int r0f = tid >> 2;           // 0..127 (each thread: one 16B seg per tile)
    const int segf = tid & 3;

    float acc[2][4][4];
    #pragma unroll
    for (int mf = 0; mf < 2; mf++)
        #pragma unroll
        for (int nf = 0; nf < 4; nf++)
            #pragma unroll
            for (int j = 0; j < 4; j++) acc[mf][nf][j] = 0.f;

    // lane components of ldsm addresses
    const uint32_t a_lane = (uint32_t)((wm + (lane & 15)) * 80 + ((lane >> 4) * 8) * 2);
    const uint32_t b_lane = (uint32_t)((wn + (lane & 7) + ((lane >> 4) & 1) * 8) * 80 +
                                       (((lane >> 3) & 1) * 8) * 2);

    auto issue_stage = [&](int stage, int k0) {
        const uint32_t st = sbase + (uint32_t)stage * STAGE_B;
        #pragma unroll
        for (int t = 0; t < 4; t++) {
            cp_async16(st + (uint32_t)(t * TILE_B + r0f * 80 + segf * 16),
                       gsrc[t] + (long)r0f * glds[t] + k0 + segf * 8);
        }
    };

    // prologue: stages 0,1 in flight; wait stage 0; start stage 2
    issue_stage(0, 0);  CP_COMMIT();
    issue_stage(1, BK); CP_COMMIT();
    CP_WAIT1();
    __syncthreads();

    const int nch = K / BK;
    if (nch > 2) issue_stage(2, 2 * BK);
    CP_COMMIT();

    for (int c = 0; c < nch; c++) {
        const uint32_t st = sbase + (uint32_t)(c % NSTAGE) * STAGE_B;

        #pragma unroll
        for (int ks = 0; ks < 2; ks++) {
            uint32_t ah[2][4], al[2][4], bh[4][2], bl[4][2];
            const uint32_t aoff = st + a_lane + (uint32_t)(ks * 32);
            #pragma unroll
            for (int mf = 0; mf < 2; mf++) {
                ldsm4(ah[mf], aoff + (uint32_t)(mf * 16 * 80));
                ldsm4(al[mf], aoff + TILE_B + (uint32_t)(mf * 16 * 80));
            }
            const uint32_t boff = st + 2 * TILE_B + b_lane + (uint32_t)(ks * 32);
            #pragma unroll
            for (int np = 0; np < 2; np++) {
                uint32_t r[4];
                ldsm4(r, boff + (uint32_t)(np * 16 * 80));
                bh[np * 2][0] = r[0]; bh[np * 2][1] = r[1];
                bh[np * 2 + 1][0] = r[2]; bh[np * 2 + 1][1] = r[3];
                ldsm4(r, boff + TILE_B + (uint32_t)(np * 16 * 80));
                bl[np * 2][0] = r[0]; bl[np * 2][1] = r[1];
                bl[np * 2 + 1][0] = r[2]; bl[np * 2 + 1][1] = r[3];
            }
            // TERM-OUTERMOST: 8 independent accs between same-acc reuses
            #pragma unroll
            for (int mf = 0; mf < 2; mf++)
                #pragma unroll
                for (int nf = 0; nf < 4; nf++)
                    mma_bf16(acc[mf][nf], ah[mf], bh[nf]);
            #pragma unroll
            for (int mf = 0; mf < 2; mf++)
                #pragma unroll
                for (int nf = 0; nf < 4; nf++)
                    mma_bf16(acc[mf][nf], ah[mf], bl[nf]);
            #pragma unroll
            for (int mf = 0; mf < 2; mf++)
                #pragma unroll
                for (int nf = 0; nf < 4; nf++)
                    mma_bf16(acc[mf][nf], al[mf], bh[nf]);
        }

        if (c + 1 < nch) {
            CP_WAIT1();                 // stage c+1 copies retired
            __syncthreads();            // visible to all; stage c%3 free to refill
            if (c + 3 < nch) issue_stage((c + 3) % NSTAGE, (c + 3) * BK);
            CP_COMMIT();
        }
    }

    // ---- epilogue ----
    float* Cfb = Cf ? Cf + (long)z * sC : nullptr;
    __nv_bfloat16* Chb = Ch ? Ch + (long)z * sC : nullptr;
    __nv_bfloat16* Clb = Cl ? Cl + (long)z * sC : nullptr;

    #pragma unroll
    for (int mf = 0; mf < 2; mf++) {
        #pragma unroll
        for (int nf = 0; nf < 4; nf++) {
            const int r0 = rowBase + wm + mf * 16 + (lane >> 2);
            const int c0 = colBase + wn + nf * 8 + 2 * (lane & 3);
            const float b0 = bias ? bias[c0] : 0.f;
            const float b1 = bias ? bias[c0 + 1] : 0.f;
            const float v00 = acc[mf][nf][0] + b0;
            const float v01 = acc[mf][nf][1] + b1;
            const float v10 = acc[mf][nf][2] + b0;
            const float v11 = acc[mf][nf][3] + b1;
            if (Cfb) {
                *reinterpret_cast<float2*>(&Cfb[(long)r0 * ldc + c0]) = make_float2(v00, v01);
                *reinterpret_cast<float2*>(&Cfb[(long)(r0 + 8) * ldc + c0]) = make_float2(v10, v11);
            }
            if (Chb) {
                __nv_bfloat162 h2, l2;
                h2.x = __float2bfloat16(v00);
                h2.y = __float2bfloat16(v01);
                l2.x = __float2bfloat16(v00 - __bfloat162float(h2.x));
                l2.y = __float2bfloat16(v01 - __bfloat162float(h2.y));
                *reinterpret_cast<__nv_bfloat162*>(&Chb[(long)r0 * ldc + c0]) = h2;
                *reinterpret_cast<__nv_bfloat162*>(&Clb[(long)r0 * ldc + c0]) = l2;
                h2.x = __float2bfloat16(v10);
                h2.y = __float2bfloat16(v11);
                l2.x = __float2bfloat16(v10 - __bfloat162float(h2.x));
                l2.y = __float2bfloat16(v11 - __bfloat162float(h2.y));
                *reinterpret_cast<__nv_bfloat162*>(&Chb[(long)(r0 + 8) * ldc + c0]) = h2;
                *reinterpret_cast<__nv_bfloat162*>(&Clb[(long)(r0 + 8) * ldc + c0]) = l2;
            }
        }
    }
}

// ============================================================================
// fused combined + softmax (in-place fp32) + bf16 hi/lo output for attn@V
// combined = 0.7*score/128 + 0.3*(log(Z) - (Tq+Tk)/Z - 1.6e-7), Z = Sq_i + Sk_j
// ============================================================================
__global__ __launch_bounds__(256)
void softmax_kernel(float* __restrict__ attn,
                    __nv_bfloat16* __restrict__ ahi, __nv_bfloat16* __restrict__ alo,
                    const float* __restrict__ Sq, const float* __restrict__ Tq,
                    const float* __restrict__ Sk, const float* __restrict__ Tk)
{
    const int row = blockIdx.x;      // 0..4095
    const int b = row >> 10;
    float* a = attn + (size_t)row * SS;
    __nv_bfloat16* ah = ahi + (size_t)row * SS;
    __nv_bfloat16* al = alo + (size_t)row * SS;
    const float sq = Sq[row], tq = Tq[row];
    const float* skb = Sk + b * SS;
    const float* tkb = Tk + b * SS;
    const int tid = threadIdx.x;

    float c[4];
    float mx = -1e30f;
    #pragma unroll
    for (int u = 0; u < 4; u++) {
        int j = tid + u * 256;
        float Z = sq + skb[j];
        float ent = __logf(Z) - (tq + tkb[j]) / Z - 1.6e-7f;
        float v = 0.7f * (a[j] * (1.0f / 128.0f)) + 0.3f * ent;
        c[u] = v;
        mx = fmaxf(mx, v);
    }

    __shared__ float red[256];
    red[tid] = mx;
    __syncthreads();
    for (int s = 128; s > 0; s >>= 1) {
        if (tid < s) red[tid] = fmaxf(red[tid], red[tid + s]);
        __syncthreads();
    }
    mx = red[0];
    __syncthreads();

    float sum = 0.f;
    #pragma unroll
    for (int u = 0; u < 4; u++) {
        c[u] = __expf(c[u] - mx);
        sum += c[u];
    }
    red[tid] = sum;
    __syncthreads();
    for (int s = 128; s > 0; s >>= 1) {
        if (tid < s) red[tid] += red[tid + s];
        __syncthreads();
    }
    const float inv = 1.0f / red[0];

    #pragma unroll
    for (int u = 0; u < 4; u++) {
        int j = tid + u * 256;
        float f = c[u] * inv;
        a[j] = f;
        __nv_bfloat16 h = __float2bfloat16(f);
        ah[j] = h;
        al[j] = __float2bfloat16(f - __bfloat162float(h));
    }
}

// ============================================================================
// launch
// ============================================================================
extern "C" void kernel_launch(void* const* d_in, const int* in_sizes, int n_in,
                              void* d_out, int out_size)
{
    const float* query = (const float*)d_in[0];
    const float* key   = (const float*)d_in[1];
    const float* value = (const float*)d_in[2];
    const float* Wq = (const float*)d_in[3];
    const float* bq = (const float*)d_in[4];
    const float* Wk = (const float*)d_in[5];
    const float* bk = (const float*)d_in[6];
    const float* Wv = (const float*)d_in[7];
    const float* bv = (const float*)d_in[8];
    const float* Wo = (const float*)d_in[9];
    const float* bo = (const float*)d_in[10];

    float* out  = (float*)d_out;            // [B,S,D]
    float* attn = out + ELEMS;              // [B,S,S]

    cudaFuncSetAttribute(tc_gemm, cudaFuncAttributeMaxDynamicSharedMemorySize, SMEM_REQ);

    auto sym = [](const void* s) {
        void* p = nullptr;
        cudaGetSymbolAddress(&p, s);
        return p;
    };
    __nv_bfloat16* Xh  = (__nv_bfloat16*)sym(g_Xh);  __nv_bfloat16* Xl  = (__nv_bfloat16*)sym(g_Xl);
    __nv_bfloat16* Wh  = (__nv_bfloat16*)sym(g_Wh);  __nv_bfloat16* Wl  = (__nv_bfloat16*)sym(g_Wl);
    __nv_bfloat16* Ph  = (__nv_bfloat16*)sym(g_Ph);  __nv_bfloat16* Pl  = (__nv_bfloat16*)sym(g_Pl);
    __nv_bfloat16* Vth = (__nv_bfloat16*)sym(g_Vth); __nv_bfloat16* Vtl = (__nv_bfloat16*)sym(g_Vtl);
    __nv_bfloat16* Ahh = (__nv_bfloat16*)sym(g_Ah);  __nv_bfloat16* All = (__nv_bfloat16*)sym(g_Al);
    __nv_bfloat16* AVh = (__nv_bfloat16*)sym(g_AVh); __nv_bfloat16* AVl = (__nv_bfloat16*)sym(g_AVl);
    float* pSq = (float*)sym(g_Sq); float* pTq = (float*)sym(g_Tq);
    float* pSk = (float*)sym(g_Sk); float* pTk = (float*)sym(g_Tk);

    const int NE = (int)ELEMS;

    // 1) entropy stats + fused input/weight splits
    stats_kernel<<<BS / 256, 256>>>(query, key, pSq, pTq, pSk, pTk);
    convert_kernel<<<dim3(NE / 1024, 1, 3), 256>>>(query, key, value, value, Xh, Xl, NE);
    convert_kernel<<<dim3(NW / 1024, 1, 4), 256>>>(Wq, Wk, Wv, Wo, Wh, Wl, NW);

    // 2) fused Q/K/V projections: X[z] @ W[z]^T + b[z]   (z = 0,1,2)
    dim3 gp(DD / BN, BS / BM, 3);
    tc_gemm<<<gp, 512, SMEM_REQ>>>(Xh, Xl, DD, Wh, Wl, DD, bq, bk, bv, 1,
                                   nullptr, Ph, Pl, DD, DD,
                                   (long)ELEMS, (long)NW, (long)ELEMS);

    // 3) V^T hi+lo in one launch ([N=d, K=t] row-major for attn@V)
    dim3 gt(DD / 32, SS / 32, 2 * BB);
    transpose_kernel<<<gt, dim3(32, 8)>>>(Ph + 2 * ELEMS, Pl + 2 * ELEMS, Vth, Vtl);

    // 4) scores S = Q @ K^T per batch -> fp32 into attn buffer
    dim3 gs(SS / BN, SS / BM, BB);
    tc_gemm<<<gs, 512, SMEM_REQ>>>(Ph, Pl, DD, Ph + ELEMS, Pl + ELEMS, DD,
                                   nullptr, nullptr, nullptr, 0,
                                   attn, nullptr, nullptr, SS,
                                   DD, (long)SS * DD, (long)SS * DD, (long)SS * SS);

    // 5) fused combined + softmax (in place) + bf16 split attn
    softmax_kernel<<<BS, 256>>>(attn, Ahh, All, pSq, pTq, pSk, pTk);

    // 6) AV = attn @ V per batch (B = V^T, K-major over t)
    tc_gemm<<<gs, 512, SMEM_REQ>>>(Ahh, All, SS, Vth, Vtl, SS,
                                   nullptr, nullptr, nullptr, 0,
                                   nullptr, AVh, AVl, DD,
                                   SS, (long)SS * SS, (long)SS * DD, (long)SS * DD);

    // 7) output = AV @ Wo^T + bo
    dim3 go(DD / BN, BS / BM, 1);
    tc_gemm<<<go, 512, SMEM_REQ>>>(AVh, AVl, DD, Wh + 3 * (size_t)NW, Wl + 3 * (size_t)NW, DD,
                                   bo, nullptr, nullptr, 0,
                                   out, nullptr, nullptr, DD, DD, 0, 0, 0);
}